// round 5
// baseline (speedup 1.0000x reference)
#include <cuda_runtime.h>
#include <cuda_bf16.h>
#include <math_constants.h>

// RWKV WKV scan. B=8, S=2048, H=2048.
// R4: chunked associative scan, 4-wide vectorized (each thread owns 4 adjacent
// h-channels; all k/v/out traffic is LDG.128/STG.128). CHUNKS=16.
//   K1: per-chunk state summaries from identity.
//   K2: per-channel prefix combine over 16 summaries.
//   K3: outputs from exact chunk-entry state (re-reads k,v).

#define WKV_B 8
#define WKV_S 2048
#define WKV_H 2048
#define BH    (WKV_B * WKV_H)      // 16384
#define CHUNKS 16
#define CLEN  (WKV_S / CHUNKS)     // 128
#define QBH   (BH / 4)             // 4096 quads
#define ROWQ  (WKV_H / 4)          // 512 float4 per row

__device__ float4 g_sum_m[CHUNKS * QBH];
__device__ float4 g_sum_n[CHUNKS * QBH];
__device__ float4 g_sum_d[CHUNKS * QBH];
__device__ float4 g_pre_m[CHUNKS * QBH];
__device__ float4 g_pre_n[CHUNKS * QBH];
__device__ float4 g_pre_d[CHUNKS * QBH];

__device__ __forceinline__ float ex2(float x) {
    float r;
    asm("ex2.approx.ftz.f32 %0, %1;" : "=f"(r) : "f"(x));
    return r;
}

#define L2E 1.4426950408889634f

// One state-update step for 4 channels.
__device__ __forceinline__ void state_step4(
    const float4 k4, const float4 v4,
    const float td[4], float m[4], float num[4], float den[4])
{
    const float* kf = (const float*)&k4;
    const float* vf = (const float*)&v4;
#pragma unroll
    for (int j = 0; j < 4; ++j) {
        const float kt = kf[j] * L2E;
        const float vt = vf[j];
        const float a  = m[j] + td[j];
        const float d2 = a - kt;
        const float es = ex2(-fabsf(d2));
        const float e1 = (d2 >= 0.0f) ? 1.0f : es;
        const float e2 = (d2 >= 0.0f) ? es : 1.0f;
        m[j]   = fmaxf(a, kt);
        num[j] = fmaf(e1, num[j], e2 * vt);
        den[j] = fmaf(e1, den[j], e2);
    }
}

// ---------------- Kernel 1: chunk summaries ----------------
__global__ void __launch_bounds__(128, 4) wkv_sum_kernel(
    const float* __restrict__ time_decay,
    const float* __restrict__ k,
    const float* __restrict__ v)
{
    const int tid = blockIdx.x * blockDim.x + threadIdx.x;  // 0..CHUNKS*QBH-1
    const int c   = tid >> 12;           // QBH = 2^12
    const int q   = tid & (QBH - 1);
    const int ch0 = q << 2;
    const int h0  = ch0 & (WKV_H - 1);
    const int b   = ch0 >> 11;

    const float4 tdv = *(const float4*)(time_decay + h0);
    float td[4] = { -__expf(tdv.x) * L2E, -__expf(tdv.y) * L2E,
                    -__expf(tdv.z) * L2E, -__expf(tdv.w) * L2E };

    float m[4], num[4], den[4];
#pragma unroll
    for (int j = 0; j < 4; ++j) { m[j] = -CUDART_INF_F; num[j] = 0.0f; den[j] = 0.0f; }

    const size_t base = (size_t)b * (WKV_S * WKV_H) + (size_t)(c * CLEN) * WKV_H + h0;
    const float4* __restrict__ kp = (const float4*)(k + base);
    const float4* __restrict__ vp = (const float4*)(v + base);

    float4 kb[2], vb[2];
    kb[0] = kp[0];      vb[0] = vp[0];
    kb[1] = kp[ROWQ];   vb[1] = vp[ROWQ];

    for (int t0 = 0; t0 < CLEN; t0 += 2) {
        float4 kn0, kn1, vn0, vn1;
        const bool more = (t0 + 2) < CLEN;
        if (more) {
            kn0 = kp[(t0 + 2) * ROWQ]; vn0 = vp[(t0 + 2) * ROWQ];
            kn1 = kp[(t0 + 3) * ROWQ]; vn1 = vp[(t0 + 3) * ROWQ];
        }
        state_step4(kb[0], vb[0], td, m, num, den);
        state_step4(kb[1], vb[1], td, m, num, den);
        if (more) { kb[0] = kn0; vb[0] = vn0; kb[1] = kn1; vb[1] = vn1; }
    }

    g_sum_m[tid] = make_float4(m[0], m[1], m[2], m[3]);
    g_sum_n[tid] = make_float4(num[0], num[1], num[2], num[3]);
    g_sum_d[tid] = make_float4(den[0], den[1], den[2], den[3]);
}

// ---------------- Kernel 2: per-channel prefix over chunk summaries ----------
__global__ void __launch_bounds__(256) wkv_prefix_kernel(
    const float* __restrict__ time_decay,
    const float* __restrict__ m0,
    const float* __restrict__ n0,
    const float* __restrict__ d0)
{
    const int ch = blockIdx.x * blockDim.x + threadIdx.x;   // 0..BH-1
    const int h  = ch & (WKV_H - 1);

    const float td  = -__expf(time_decay[h]) * L2E;
    const float Ltd = (float)CLEN * td;

    float pm = m0[ch] * L2E;
    float pn = n0[ch];
    float pd = d0[ch];

    const float* sm = (const float*)g_sum_m;
    const float* sn = (const float*)g_sum_n;
    const float* sd = (const float*)g_sum_d;
    float* pmem = (float*)g_pre_m;
    float* pnem = (float*)g_pre_n;
    float* pdem = (float*)g_pre_d;

#pragma unroll
    for (int c = 0; c < CHUNKS; ++c) {
        const int idx = c * BH + ch;
        pmem[idx] = pm;
        pnem[idx] = pn;
        pdem[idx] = pd;
        if (c < CHUNKS - 1) {
            const float a  = pm + Ltd;        // prefix decayed through CLEN steps
            const float mo = fmaxf(a, sm[idx]);
            const float e1 = ex2(a - mo);
            const float e2 = ex2(sm[idx] - mo);
            pn = fmaf(e1, pn, e2 * sn[idx]);
            pd = fmaf(e1, pd, e2 * sd[idx]);
            pm = mo;
        }
    }
}

// ---------------- Kernel 3: outputs from exact chunk-entry state -------------
__global__ void __launch_bounds__(128, 4) wkv_out_kernel(
    const float* __restrict__ time_decay,
    const float* __restrict__ k,
    const float* __restrict__ time_first,
    const float* __restrict__ v,
    float* __restrict__ out)
{
    const int tid = blockIdx.x * blockDim.x + threadIdx.x;
    const int c   = tid >> 12;
    const int q   = tid & (QBH - 1);
    const int ch0 = q << 2;
    const int h0  = ch0 & (WKV_H - 1);
    const int b   = ch0 >> 11;

    const float4 tdv = *(const float4*)(time_decay + h0);
    const float4 tfv = *(const float4*)(time_first + h0);
    float td[4] = { -__expf(tdv.x) * L2E, -__expf(tdv.y) * L2E,
                    -__expf(tdv.z) * L2E, -__expf(tdv.w) * L2E };
    float tf[4] = { tfv.x * L2E, tfv.y * L2E, tfv.z * L2E, tfv.w * L2E };

    const float4 pm4 = g_pre_m[tid];
    const float4 pn4 = g_pre_n[tid];
    const float4 pd4 = g_pre_d[tid];
    float m[4]   = { pm4.x, pm4.y, pm4.z, pm4.w };
    float num[4] = { pn4.x, pn4.y, pn4.z, pn4.w };
    float den[4] = { pd4.x, pd4.y, pd4.z, pd4.w };

    const size_t base = (size_t)b * (WKV_S * WKV_H) + (size_t)(c * CLEN) * WKV_H + h0;
    const float4* __restrict__ kp = (const float4*)(k + base);
    const float4* __restrict__ vp = (const float4*)(v + base);
    float4* __restrict__ op = (float4*)(out + base);

    float4 kb[2], vb[2];
    kb[0] = kp[0];      vb[0] = vp[0];
    kb[1] = kp[ROWQ];   vb[1] = vp[ROWQ];

    for (int t0 = 0; t0 < CLEN; t0 += 2) {
        float4 kn0, kn1, vn0, vn1;
        const bool more = (t0 + 2) < CLEN;
        if (more) {
            kn0 = kp[(t0 + 2) * ROWQ]; vn0 = vp[(t0 + 2) * ROWQ];
            kn1 = kp[(t0 + 3) * ROWQ]; vn1 = vp[(t0 + 3) * ROWQ];
        }
#pragma unroll
        for (int u = 0; u < 2; ++u) {
            const float* kf = (const float*)&kb[u];
            const float* vf = (const float*)&vb[u];
            float4 o4;
            float* of = (float*)&o4;
#pragma unroll
            for (int j = 0; j < 4; ++j) {
                const float kt = kf[j] * L2E;
                const float vt = vf[j];

                // output branch
                const float btf = kt + tf[j];
                const float d1  = m[j] - btf;
                const float eo  = ex2(-fabsf(d1));
                const float e1o = (d1 >= 0.0f) ? 1.0f : eo;
                const float e2o = (d1 >= 0.0f) ? eo : 1.0f;
                const float on  = fmaf(e1o, num[j], e2o * vt);
                const float od  = fmaf(e1o, den[j], e2o);
                of[j] = __fdividef(on, od);

                // state branch
                const float a  = m[j] + td[j];
                const float d2 = a - kt;
                const float es = ex2(-fabsf(d2));
                const float e1 = (d2 >= 0.0f) ? 1.0f : es;
                const float e2 = (d2 >= 0.0f) ? es : 1.0f;
                m[j]   = fmaxf(a, kt);
                num[j] = fmaf(e1, num[j], e2 * vt);
                den[j] = fmaf(e1, den[j], e2);
            }
            op[(t0 + u) * ROWQ] = o4;
        }
        if (more) { kb[0] = kn0; vb[0] = vn0; kb[1] = kn1; vb[1] = vn1; }
    }

    if (c == CHUNKS - 1) {
        float* st = out + (size_t)WKV_B * WKV_S * WKV_H;
        *(float4*)(st + ch0) = make_float4(m[0] * (1.0f / L2E), m[1] * (1.0f / L2E),
                                           m[2] * (1.0f / L2E), m[3] * (1.0f / L2E));
        *(float4*)(st + BH + ch0)     = make_float4(num[0], num[1], num[2], num[3]);
        *(float4*)(st + 2 * BH + ch0) = make_float4(den[0], den[1], den[2], den[3]);
    }
}

extern "C" void kernel_launch(void* const* d_in, const int* in_sizes, int n_in,
                              void* d_out, int out_size) {
    const float* time_decay = (const float*)d_in[0];
    const float* key        = (const float*)d_in[1];
    const float* time_first = (const float*)d_in[2];
    const float* value      = (const float*)d_in[3];
    const float* max_state  = (const float*)d_in[4];
    const float* num_state  = (const float*)d_in[5];
    const float* den_state  = (const float*)d_in[6];
    float* out = (float*)d_out;

    const int total = CHUNKS * QBH;       // 65536 threads
    wkv_sum_kernel<<<total / 128, 128>>>(time_decay, key, value);
    wkv_prefix_kernel<<<BH / 256, 256>>>(time_decay, max_state, num_state, den_state);
    wkv_out_kernel<<<total / 128, 128>>>(time_decay, key, time_first, value, out);
}

// round 6
// speedup vs baseline: 1.2388x; 1.2388x over previous
#include <cuda_runtime.h>
#include <cuda_bf16.h>
#include <math_constants.h>

// RWKV WKV scan. B=8, S=2048, H=2048.
// R5: single-pass chunked scan with decoupled lookback.
// Block (g,c): 512 channels x 16 steps. Load k,v tile -> SMEM once, local scan
// (identity) -> publish aggregate, lookback to get exact entry state, publish
// inclusive, then output pass from SMEM. k,v read from DRAM exactly once.

#define S_   2048
#define H_   2048
#define B_   8
#define BH_  (B_ * H_)        // 16384 channels
#define CLEN 16               // steps per chunk
#define CC   (S_ / CLEN)      // 128 chunks
#define GCH  512              // channels per group
#define GROUPS (BH_ / GCH)    // 32
#define NT   128              // threads per block (4 channels each)
#define ROWQ (H_ / 4)         // 512 float4 per row

#define L2E 1.4426950408889634f

// Scratch (status-guarded; reset kernel clears status each launch).
__device__ float4 g_aggm[GROUPS * CC * NT];
__device__ float4 g_aggn[GROUPS * CC * NT];
__device__ float4 g_aggd[GROUPS * CC * NT];
__device__ float4 g_incm[GROUPS * CC * NT];
__device__ float4 g_incn[GROUPS * CC * NT];
__device__ float4 g_incd[GROUPS * CC * NT];
__device__ int    g_status[GROUPS * CC];   // 0=none, 1=aggregate, 2=inclusive

__device__ __forceinline__ float ex2(float x) {
    float r;
    asm("ex2.approx.ftz.f32 %0, %1;" : "=f"(r) : "f"(x));
    return r;
}
__device__ __forceinline__ int ld_acquire(const int* p) {
    int v;
    asm volatile("ld.acquire.gpu.global.b32 %0, [%1];" : "=r"(v) : "l"(p));
    return v;
}
__device__ __forceinline__ void st_release(int* p, int v) {
    asm volatile("st.release.gpu.global.b32 [%0], %1;" :: "l"(p), "r"(v) : "memory");
}

__global__ void wkv_reset() {
    const int i = blockIdx.x * blockDim.x + threadIdx.x;
    if (i < GROUPS * CC) g_status[i] = 0;
}

__global__ void __launch_bounds__(NT, 3) wkv_main(
    const float* __restrict__ time_decay,
    const float* __restrict__ k,
    const float* __restrict__ time_first,
    const float* __restrict__ v,
    const float* __restrict__ m0,
    const float* __restrict__ n0,
    const float* __restrict__ d0,
    float* __restrict__ out)
{
    extern __shared__ float4 sh[];
    float4* ks = sh;                 // [CLEN][NT], k pre-scaled by L2E
    float4* vs = sh + CLEN * NT;     // [CLEN][NT]
    __shared__ int s_st;

    const int tid = threadIdx.x;
    const int g   = blockIdx.x & (GROUPS - 1);
    const int c   = blockIdx.x >> 5;           // GROUPS = 32
    const int ch0 = g * GCH + 4 * tid;
    const int h0  = ch0 & (H_ - 1);
    const int b   = ch0 >> 11;

    const float4 tdv = *(const float4*)(time_decay + h0);
    float td[4] = { -__expf(tdv.x) * L2E, -__expf(tdv.y) * L2E,
                    -__expf(tdv.z) * L2E, -__expf(tdv.w) * L2E };

    const size_t baseq =
        ((size_t)b * S_ * H_ + (size_t)c * CLEN * H_ + (size_t)h0) >> 2;
    const float4* __restrict__ kp = (const float4*)k + baseq;
    const float4* __restrict__ vp = (const float4*)v + baseq;

    // ---------------- Phase 1: load tile + local scan from identity ----------
    float am[4], an[4], ad[4];
#pragma unroll
    for (int j = 0; j < 4; ++j) { am[j] = -CUDART_INF_F; an[j] = 0.f; ad[j] = 0.f; }

    float4 kb[4], vb[4];
#pragma unroll
    for (int r = 0; r < 4; ++r) { kb[r] = kp[r * ROWQ]; vb[r] = vp[r * ROWQ]; }

#pragma unroll 4
    for (int r = 0; r < CLEN; ++r) {
        const int slot = r & 3;
        float4 k4 = kb[slot];
        const float4 v4 = vb[slot];
        if (r + 4 < CLEN) { kb[slot] = kp[(r + 4) * ROWQ]; vb[slot] = vp[(r + 4) * ROWQ]; }
        k4.x *= L2E; k4.y *= L2E; k4.z *= L2E; k4.w *= L2E;
        ks[r * NT + tid] = k4;
        vs[r * NT + tid] = v4;
        const float* kf = (const float*)&k4;
        const float* vf = (const float*)&v4;
#pragma unroll
        for (int j = 0; j < 4; ++j) {
            const float a  = am[j] + td[j];
            const float d2 = a - kf[j];
            const float es = ex2(-fabsf(d2));
            const float e1 = (d2 >= 0.f) ? 1.f : es;
            const float e2 = (d2 >= 0.f) ? es : 1.f;
            am[j] = fmaxf(a, kf[j]);
            an[j] = fmaf(e1, an[j], e2 * vf[j]);
            ad[j] = fmaf(e1, ad[j], e2);
        }
    }

    // ---------------- Phase 2: publish + lookback -> entry state -------------
    const int gi = g * CC + c;
    const int qi = gi * NT + tid;
    float exm[4], exn[4], exd[4];   // exclusive (entry) state for this chunk

    if (c == 0) {
        const float4 mm = *(const float4*)(m0 + ch0);
        const float4 nn = *(const float4*)(n0 + ch0);
        const float4 dd = *(const float4*)(d0 + ch0);
        exm[0] = mm.x * L2E; exm[1] = mm.y * L2E; exm[2] = mm.z * L2E; exm[3] = mm.w * L2E;
        exn[0] = nn.x; exn[1] = nn.y; exn[2] = nn.z; exn[3] = nn.w;
        exd[0] = dd.x; exd[1] = dd.y; exd[2] = dd.z; exd[3] = dd.w;
    } else {
        // Publish aggregate early so successors can make progress.
        g_aggm[qi] = make_float4(am[0], am[1], am[2], am[3]);
        g_aggn[qi] = make_float4(an[0], an[1], an[2], an[3]);
        g_aggd[qi] = make_float4(ad[0], ad[1], ad[2], ad[3]);
        __syncthreads();
        if (tid == 0) st_release(&g_status[gi], 1);

        // Lookback: suffix = identity; walk idx = c-1 downward.
        float sm[4], sn[4], sd[4];
#pragma unroll
        for (int j = 0; j < 4; ++j) { sm[j] = -CUDART_INF_F; sn[j] = 0.f; sd[j] = 0.f; }
        float slen = 0.f;
        int idx = gi - 1;

        for (;;) {
            if (tid == 0) {
                int s;
                while ((s = ld_acquire(&g_status[idx])) == 0) __nanosleep(60);
                s_st = s;
            }
            __syncthreads();
            const int s = s_st;
            __syncthreads();
            const int q2 = idx * NT + tid;
            if (s == 1) {
                // suffix = compose(agg(idx), suffix)  [agg earlier, suffix later]
                const float4 A_m = g_aggm[q2];
                const float4 A_n = g_aggn[q2];
                const float4 A_d = g_aggd[q2];
                const float* Amf = (const float*)&A_m;
                const float* Anf = (const float*)&A_n;
                const float* Adf = (const float*)&A_d;
#pragma unroll
                for (int j = 0; j < 4; ++j) {
                    const float a  = Amf[j] + slen * td[j];
                    const float mo = fmaxf(a, sm[j]);
                    const float e1 = ex2(a - mo);
                    const float e2 = ex2(sm[j] - mo);
                    sn[j] = fmaf(e1, Anf[j], e2 * sn[j]);
                    sd[j] = fmaf(e1, Adf[j], e2 * sd[j]);
                    sm[j] = mo;
                }
                slen += (float)CLEN;
                --idx;
            } else {
                // exclusive = compose(inclusive(idx), suffix)
                const float4 E_m = g_incm[q2];
                const float4 E_n = g_incn[q2];
                const float4 E_d = g_incd[q2];
                const float* Emf = (const float*)&E_m;
                const float* Enf = (const float*)&E_n;
                const float* Edf = (const float*)&E_d;
#pragma unroll
                for (int j = 0; j < 4; ++j) {
                    const float a  = Emf[j] + slen * td[j];
                    const float mo = fmaxf(a, sm[j]);
                    const float e1 = ex2(a - mo);
                    const float e2 = ex2(sm[j] - mo);
                    exn[j] = fmaf(e1, Enf[j], e2 * sn[j]);
                    exd[j] = fmaf(e1, Edf[j], e2 * sd[j]);
                    exm[j] = mo;
                }
                break;
            }
        }
    }

    // inclusive(c) = compose(exclusive, own aggregate over CLEN steps)
    {
        float im[4], in_[4], id_[4];
#pragma unroll
        for (int j = 0; j < 4; ++j) {
            const float a  = exm[j] + (float)CLEN * td[j];
            const float mo = fmaxf(a, am[j]);
            const float e1 = ex2(a - mo);
            const float e2 = ex2(am[j] - mo);
            in_[j] = fmaf(e1, exn[j], e2 * an[j]);
            id_[j] = fmaf(e1, exd[j], e2 * ad[j]);
            im[j]  = mo;
        }
        g_incm[qi] = make_float4(im[0], im[1], im[2], im[3]);
        g_incn[qi] = make_float4(in_[0], in_[1], in_[2], in_[3]);
        g_incd[qi] = make_float4(id_[0], id_[1], id_[2], id_[3]);
        __syncthreads();
        if (tid == 0) st_release(&g_status[gi], 2);
    }

    // ---------------- Phase 3: outputs from exact entry state ----------------
    const float4 tfv = *(const float4*)(time_first + h0);
    float tf[4] = { tfv.x * L2E, tfv.y * L2E, tfv.z * L2E, tfv.w * L2E };

    float m[4], num[4], den[4];
#pragma unroll
    for (int j = 0; j < 4; ++j) { m[j] = exm[j]; num[j] = exn[j]; den[j] = exd[j]; }

    float4* __restrict__ op = (float4*)out + baseq;

#pragma unroll 4
    for (int r = 0; r < CLEN; ++r) {
        const float4 k4 = ks[r * NT + tid];   // pre-scaled by L2E
        const float4 v4 = vs[r * NT + tid];
        const float* kf = (const float*)&k4;
        const float* vf = (const float*)&v4;
        float4 o4;
        float* of = (float*)&o4;
#pragma unroll
        for (int j = 0; j < 4; ++j) {
            const float kt = kf[j];
            const float vt = vf[j];

            // output branch
            const float btf = kt + tf[j];
            const float d1  = m[j] - btf;
            const float eo  = ex2(-fabsf(d1));
            const float e1o = (d1 >= 0.f) ? 1.f : eo;
            const float e2o = (d1 >= 0.f) ? eo : 1.f;
            const float on  = fmaf(e1o, num[j], e2o * vt);
            const float od  = fmaf(e1o, den[j], e2o);
            of[j] = __fdividef(on, od);

            // state branch
            const float a  = m[j] + td[j];
            const float d2 = a - kt;
            const float es = ex2(-fabsf(d2));
            const float e1 = (d2 >= 0.f) ? 1.f : es;
            const float e2 = (d2 >= 0.f) ? es : 1.f;
            m[j]   = fmaxf(a, kt);
            num[j] = fmaf(e1, num[j], e2 * vt);
            den[j] = fmaf(e1, den[j], e2);
        }
        op[r * ROWQ] = o4;
    }

    if (c == CC - 1) {
        float* st = out + (size_t)B_ * S_ * H_;
        *(float4*)(st + ch0) = make_float4(m[0] * (1.f / L2E), m[1] * (1.f / L2E),
                                           m[2] * (1.f / L2E), m[3] * (1.f / L2E));
        *(float4*)(st + BH_ + ch0)     = make_float4(num[0], num[1], num[2], num[3]);
        *(float4*)(st + 2 * BH_ + ch0) = make_float4(den[0], den[1], den[2], den[3]);
    }
}

extern "C" void kernel_launch(void* const* d_in, const int* in_sizes, int n_in,
                              void* d_out, int out_size) {
    const float* time_decay = (const float*)d_in[0];
    const float* key        = (const float*)d_in[1];
    const float* time_first = (const float*)d_in[2];
    const float* value      = (const float*)d_in[3];
    const float* max_state  = (const float*)d_in[4];
    const float* num_state  = (const float*)d_in[5];
    const float* den_state  = (const float*)d_in[6];
    float* out = (float*)d_out;

    const int smem = 2 * CLEN * NT * sizeof(float4);   // 64 KB
    cudaFuncSetAttribute(wkv_main, cudaFuncAttributeMaxDynamicSharedMemorySize, smem);

    wkv_reset<<<(GROUPS * CC + 255) / 256, 256>>>();
    wkv_main<<<GROUPS * CC, NT, smem>>>(time_decay, key, time_first, value,
                                        max_state, num_state, den_state, out);
}